// round 10
// baseline (speedup 1.0000x reference)
#include <cuda_runtime.h>
#include <cuda_bf16.h>
#include <cstdint>

typedef unsigned long long ull;

// B=64, T=1024, TF=512, S=1536, D=512, F=32
#define NROW 65536
#define INV_SCALE 0.04419417382415922f   // 1/sqrt(512)
#define LOG2E 1.4426950408889634f
#define CE_F (INV_SCALE * LOG2E)

// ---------------- scratch (static __device__, no allocs) ----------------
__device__ __nv_bfloat16 g_PmTb[64 * 512];           // PmT[n][c]: n<32 = A col, n>=32 = CC col
__device__ float g_c1[32];
__device__ float g_vb[512];
__device__ __nv_bfloat16 g_qzb[(size_t)NROW * 64];   // per row: qk*CE+c1*CE [32] | z [32]
__device__ __nv_bfloat16 g_wbf[(size_t)64 * 1536 * 32];
__device__ float g_h[NROW];
__device__ float g_pd[2 * NROW];                     // partial den (s-halves)
__device__ float g_pn[2 * NROW];                     // partial num
__device__ float g_P[NROW];
__device__ float g_fp[16 * 64 * 512];                // partial final sums (16 t-chunks)
__device__ float g_final[64 * 512];

// ---------------- helpers ----------------
__device__ __forceinline__ float ex2f(float x) {
    float r; asm("ex2.approx.ftz.f32 %0, %1;" : "=f"(r) : "f"(x)); return r;
}

// m16n8k16 row.col bf16 -> f32 (sm_80+, no arch-specific suffix)
__device__ __forceinline__ void mma16816(float& d0, float& d1, float& d2, float& d3,
                                         uint32_t a0, uint32_t a1, uint32_t a2, uint32_t a3,
                                         uint32_t b0, uint32_t b1) {
    asm volatile("mma.sync.aligned.m16n8k16.row.col.f32.bf16.bf16.f32 "
                 "{%0,%1,%2,%3}, {%4,%5,%6,%7}, {%8,%9}, {%0,%1,%2,%3};"
                 : "+f"(d0), "+f"(d1), "+f"(d2), "+f"(d3)
                 : "r"(a0), "r"(a1), "r"(a2), "r"(a3), "r"(b0), "r"(b1));
}

__device__ __forceinline__ uint32_t packbf(float2 p) {
    __nv_bfloat162 v = __floats2bfloat162_rn(p.x, p.y);
    return *(uint32_t*)&v;
}

// ---------------------------------------------------------------------------
// K0: weight precompute.  grid=512 (c), block=128.
// ---------------------------------------------------------------------------
__global__ __launch_bounds__(128) void k0(
    const float* __restrict__ Wq, const float* __restrict__ bq,
    const float* __restrict__ Wk, const float* __restrict__ Wv,
    const float* __restrict__ bv, const float* __restrict__ Ws,
    const float* __restrict__ bs)
{
    __shared__ float sWq[512], sWsc[512];
    int c = blockIdx.x;
    for (int i = threadIdx.x; i < 512; i += 128) {
        sWq[i]  = Wq[c * 512 + i];
        sWsc[i] = Ws[i * 512 + c];
    }
    __syncthreads();
    int t = threadIdx.x;
    if (t < 32) {
        const float* wk = Wk + t * 512;
        float acc = 0.f;
        #pragma unroll 8
        for (int d = 0; d < 512; d++) acc = fmaf(sWq[d], wk[d], acc);
        g_PmTb[t * 512 + c] = __float2bfloat16(acc);
    } else if (t < 64) {
        const float* wv = Wv + (t - 32) * 512;
        float acc = 0.f;
        #pragma unroll 8
        for (int d = 0; d < 512; d++) acc = fmaf(wv[d], sWsc[d], acc);
        g_PmTb[t * 512 + c] = __float2bfloat16(acc);
    } else if (t == 64) {
        float acc = bs[c];
        for (int d = 0; d < 512; d++) acc = fmaf(bv[d], sWsc[d], acc);
        g_vb[c] = acc;
    } else if (t >= 96 && c == 0) {
        const float* wk = Wk + (t - 96) * 512;
        float acc = 0.f;
        for (int d = 0; d < 512; d++) acc = fmaf(bq[d], wk[d], acc);
        g_c1[t - 96] = acc;
    }
}

// ---------------------------------------------------------------------------
// K1M: qz = y @ PmT^T via bf16 mma.sync; fused h = y . vb.
// ---------------------------------------------------------------------------
__global__ __launch_bounds__(256) void k1m(const float* __restrict__ y)
{
    __shared__ __align__(16) char sB[64 * 528];   // 33792 B
    __shared__ float svb[512];
    __shared__ float sc1[32];

    int tid = threadIdx.x;
    int w = tid >> 5, lane = tid & 31;
    int g = lane >> 2, t = lane & 3;
    int R = blockIdx.x * 128 + w * 16;

    for (int i = tid; i < 512; i += 256) svb[i] = g_vb[i];
    if (tid < 32) sc1[tid] = g_c1[tid];

    float acc[8][4];
    #pragma unroll
    for (int n = 0; n < 8; n++) {
        acc[n][0] = 0.f; acc[n][1] = 0.f; acc[n][2] = 0.f; acc[n][3] = 0.f;
    }
    float ha = 0.f, hb = 0.f;

    const float* rowA = y + (size_t)(R + g) * 512;
    const float* rowB = y + (size_t)(R + g + 8) * 512;

    for (int half = 0; half < 2; half++) {
        __syncthreads();
        for (int i = tid; i < 2048; i += 256) {
            int r = i >> 5, seg = i & 31;
            *(uint4*)(sB + r * 528 + seg * 16) =
                *(const uint4*)(g_PmTb + (size_t)r * 512 + half * 256 + seg * 8);
        }
        __syncthreads();

        #pragma unroll 4
        for (int ks = 0; ks < 16; ks++) {
            int kg = half * 256 + ks * 16;
            int c  = kg + 2 * t;
            float2 p0 = *(const float2*)(rowA + c);
            float2 p1 = *(const float2*)(rowB + c);
            float2 p2 = *(const float2*)(rowA + c + 8);
            float2 p3 = *(const float2*)(rowB + c + 8);
            ha += p0.x * svb[c] + p0.y * svb[c + 1] + p2.x * svb[c + 8] + p2.y * svb[c + 9];
            hb += p1.x * svb[c] + p1.y * svb[c + 1] + p3.x * svb[c + 8] + p3.y * svb[c + 9];
            uint32_t a0 = packbf(p0), a1 = packbf(p1), a2 = packbf(p2), a3 = packbf(p3);
            const char* bbase = sB + g * 528 + 4 * t + 32 * ks;
            #pragma unroll
            for (int n = 0; n < 8; n++) {
                uint32_t b0 = *(const uint32_t*)(bbase + n * (8 * 528));
                uint32_t b1 = *(const uint32_t*)(bbase + n * (8 * 528) + 16);
                mma16816(acc[n][0], acc[n][1], acc[n][2], acc[n][3], a0, a1, a2, a3, b0, b1);
            }
        }
    }
    ha += __shfl_xor_sync(~0u, ha, 1); ha += __shfl_xor_sync(~0u, ha, 2);
    hb += __shfl_xor_sync(~0u, hb, 1); hb += __shfl_xor_sync(~0u, hb, 2);
    if (t == 0) { g_h[R + g] = ha; g_h[R + g + 8] = hb; }

    #pragma unroll
    for (int n = 0; n < 8; n++) {
        int col = n * 8 + 2 * t;
        float add0 = (n < 4) ? sc1[col] : 0.f;
        float add1 = (n < 4) ? sc1[col + 1] : 0.f;
        float sc   = (n < 4) ? CE_F : 1.0f;
        float v00 = (acc[n][0] + add0) * sc, v01 = (acc[n][1] + add1) * sc;
        float v10 = (acc[n][2] + add0) * sc, v11 = (acc[n][3] + add1) * sc;
        *(__nv_bfloat162*)(g_qzb + (size_t)(R + g) * 64 + col)     = __floats2bfloat162_rn(v00, v01);
        *(__nv_bfloat162*)(g_qzb + (size_t)(R + g + 8) * 64 + col) = __floats2bfloat162_rn(v10, v11);
    }
}

// ---------------------------------------------------------------------------
// KWC: weather -> bf16 contiguous [b][1536][32] (hist then fore).
// ---------------------------------------------------------------------------
__global__ __launch_bounds__(256) void kwc(const float* __restrict__ wh,
                                           const float* __restrict__ wf)
{
    int ip = blockIdx.x * 256 + threadIdx.x;
    int b = ip / 24576;
    int r = ip - b * 24576;
    float2 v;
    if (r < 16384) v = ((const float2*)(wh + (size_t)b * 32768))[r];
    else           v = ((const float2*)(wf + (size_t)b * 16384))[r - 16384];
    ((__nv_bfloat162*)g_wbf)[(size_t)b * 24576 + r] = __floats2bfloat162_rn(v.x, v.y);
}

// ---------------------------------------------------------------------------
// K2M: micro-attention via bf16 mma.sync, s-split across blockIdx.z.
// grid (8 t-tiles, 64 b, 2 s-halves), 256 threads. Each CTA: 768 s in 3
// chunks of 256 (20 KB smem, pitch 80 B). Partial den/num -> g_pd/g_pn.
// ---------------------------------------------------------------------------
__global__ __launch_bounds__(256) void k2m()
{
    __shared__ __align__(16) char sW[256 * 80];   // 20480 B

    int tid = threadIdx.x;
    int w = tid >> 5, lane = tid & 31;
    int g = lane >> 2, t = lane & 3;
    int b = blockIdx.y;
    int z = blockIdx.z;
    size_t Rbase = (size_t)b * 1024 + blockIdx.x * 128 + w * 16;

    uint32_t qa[2][4], za[2][4];
    #pragma unroll
    for (int ks = 0; ks < 2; ks++) {
        int c = 16 * ks + 2 * t;
        qa[ks][0] = *(const uint32_t*)(g_qzb + (Rbase + g) * 64 + c);
        qa[ks][1] = *(const uint32_t*)(g_qzb + (Rbase + g + 8) * 64 + c);
        qa[ks][2] = *(const uint32_t*)(g_qzb + (Rbase + g) * 64 + c + 8);
        qa[ks][3] = *(const uint32_t*)(g_qzb + (Rbase + g + 8) * 64 + c + 8);
        za[ks][0] = *(const uint32_t*)(g_qzb + (Rbase + g) * 64 + 32 + c);
        za[ks][1] = *(const uint32_t*)(g_qzb + (Rbase + g + 8) * 64 + 32 + c);
        za[ks][2] = *(const uint32_t*)(g_qzb + (Rbase + g) * 64 + 32 + c + 8);
        za[ks][3] = *(const uint32_t*)(g_qzb + (Rbase + g + 8) * 64 + 32 + c + 8);
    }

    float dena = 0.f, numa = 0.f, denb = 0.f, numb = 0.f;

    for (int chunk = 0; chunk < 3; chunk++) {
        __syncthreads();
        const uint4* src = (const uint4*)(g_wbf + ((size_t)b * 1536 + z * 768 + chunk * 256) * 32);
        #pragma unroll
        for (int kk = 0; kk < 4; kk++) {
            int i = tid + kk * 256;
            int r = i >> 2, seg = i & 3;
            *(uint4*)(sW + r * 80 + seg * 16) = src[i];
        }
        __syncthreads();

        #pragma unroll 2
        for (int sb = 0; sb < 32; sb++) {
            const char* base = sW + (sb * 8 + g) * 80 + 4 * t;
            uint32_t b0 = *(const uint32_t*)(base);
            uint32_t b1 = *(const uint32_t*)(base + 16);
            uint32_t b2 = *(const uint32_t*)(base + 32);
            uint32_t b3 = *(const uint32_t*)(base + 48);
            float s0 = 0.f, s1 = 0.f, s2 = 0.f, s3 = 0.f;
            float z0 = 0.f, z1 = 0.f, z2 = 0.f, z3 = 0.f;
            mma16816(s0, s1, s2, s3, qa[0][0], qa[0][1], qa[0][2], qa[0][3], b0, b1);
            mma16816(s0, s1, s2, s3, qa[1][0], qa[1][1], qa[1][2], qa[1][3], b2, b3);
            mma16816(z0, z1, z2, z3, za[0][0], za[0][1], za[0][2], za[0][3], b0, b1);
            mma16816(z0, z1, z2, z3, za[1][0], za[1][1], za[1][2], za[1][3], b2, b3);
            float e0 = ex2f(s0), e1 = ex2f(s1), e2 = ex2f(s2), e3 = ex2f(s3);
            dena += e0 + e1;
            numa = fmaf(e0, z0, fmaf(e1, z1, numa));
            denb += e2 + e3;
            numb = fmaf(e2, z2, fmaf(e3, z3, numb));
        }
    }
    dena += __shfl_xor_sync(~0u, dena, 1); dena += __shfl_xor_sync(~0u, dena, 2);
    numa += __shfl_xor_sync(~0u, numa, 1); numa += __shfl_xor_sync(~0u, numa, 2);
    denb += __shfl_xor_sync(~0u, denb, 1); denb += __shfl_xor_sync(~0u, denb, 2);
    numb += __shfl_xor_sync(~0u, numb, 1); numb += __shfl_xor_sync(~0u, numb, 2);
    if (t == 0) {
        size_t r0 = Rbase + g, r1 = Rbase + g + 8;
        g_pd[(size_t)z * NROW + r0] = dena;
        g_pn[(size_t)z * NROW + r0] = numa;
        g_pd[(size_t)z * NROW + r1] = denb;
        g_pn[(size_t)z * NROW + r1] = numb;
    }
}

// ---------------------------------------------------------------------------
// K3a: combine s-halves -> logits -> P = softmax over t (per batch).
// ---------------------------------------------------------------------------
__global__ __launch_bounds__(256) void k3a()
{
    __shared__ float red[256];
    int b = blockIdx.x, tid = threadIdx.x;
    float l[4];
    #pragma unroll
    for (int k = 0; k < 4; k++) {
        size_t row = (size_t)b * 1024 + tid + 256 * k;
        float d = g_pd[row] + g_pd[NROW + row];
        float n = g_pn[row] + g_pn[NROW + row];
        l[k] = (n / d + g_h[row]) * INV_SCALE;
    }
    float m = fmaxf(fmaxf(l[0], l[1]), fmaxf(l[2], l[3]));
    red[tid] = m; __syncthreads();
    for (int o = 128; o; o >>= 1) { if (tid < o) red[tid] = fmaxf(red[tid], red[tid + o]); __syncthreads(); }
    m = red[0]; __syncthreads();
    float e[4], s = 0.f;
    #pragma unroll
    for (int k = 0; k < 4; k++) { e[k] = ex2f((l[k] - m) * LOG2E); s += e[k]; }
    red[tid] = s; __syncthreads();
    for (int o = 128; o; o >>= 1) { if (tid < o) red[tid] += red[tid + o]; __syncthreads(); }
    float inv = 1.0f / red[0];
    #pragma unroll
    for (int k = 0; k < 4; k++) g_P[b * 1024 + tid + 256 * k] = e[k] * inv;
}

// ---------------------------------------------------------------------------
// K3b: partial final sums, 16 t-chunks (occupancy fix).
// grid (16 tc, 64 b), 128 threads.
// ---------------------------------------------------------------------------
__global__ __launch_bounds__(128) void k3b(const float* __restrict__ y)
{
    int tc = blockIdx.x, b = blockIdx.y, tid = threadIdx.x;
    const float4* yb = (const float4*)(y + ((size_t)b * 1024 + tc * 64) * 512);
    const float*  Pp = g_P + b * 1024 + tc * 64;
    float4 acc = make_float4(0.f, 0.f, 0.f, 0.f);
    #pragma unroll 4
    for (int t = 0; t < 64; t++) {
        float p = Pp[t];
        float4 v = yb[(size_t)t * 128 + tid];
        acc.x = fmaf(p, v.x, acc.x); acc.y = fmaf(p, v.y, acc.y);
        acc.z = fmaf(p, v.z, acc.z); acc.w = fmaf(p, v.w, acc.w);
    }
    ((float4*)g_fp)[((size_t)tc * 64 + b) * 128 + tid] = acc;
}

// ---------------------------------------------------------------------------
// K3c: collapse 16 partials -> g_final[64*512].
// ---------------------------------------------------------------------------
__global__ __launch_bounds__(256) void k3c()
{
    int i = blockIdx.x * 256 + threadIdx.x;   // 0..32767
    float s = 0.f;
    #pragma unroll
    for (int c = 0; c < 16; c++) s += g_fp[(size_t)c * 32768 + i];
    g_final[i] = s;
}

// ---------------------------------------------------------------------------
// K4: out = y + final (broadcast over t).
// ---------------------------------------------------------------------------
__global__ __launch_bounds__(256) void k4(const float* __restrict__ y, float* __restrict__ out)
{
    size_t idx = (size_t)blockIdx.x * 256 + threadIdx.x;   // float4 index
    int b  = (int)(idx >> 17);
    int d4 = (int)(idx & 127);
    float4 f = ((const float4*)g_final)[b * 128 + d4];
    float4 v = ((const float4*)y)[idx];
    float4 o;
    o.x = v.x + f.x; o.y = v.y + f.y; o.z = v.z + f.z; o.w = v.w + f.w;
    ((float4*)out)[idx] = o;
}

// ---------------------------------------------------------------------------
extern "C" void kernel_launch(void* const* d_in, const int* in_sizes, int n_in,
                              void* d_out, int out_size)
{
    const float* y  = (const float*)d_in[0];
    const float* wh = (const float*)d_in[1];
    const float* wf = (const float*)d_in[2];
    const float* Wq = (const float*)d_in[3];
    const float* bq = (const float*)d_in[4];
    const float* Wk = (const float*)d_in[5];
    // d_in[6] = bk: cancels in softmax over s
    const float* Wv = (const float*)d_in[7];
    const float* bv = (const float*)d_in[8];
    const float* Ws = (const float*)d_in[9];
    const float* bs = (const float*)d_in[10];
    float* out = (float*)d_out;

    k0 <<<512, 128>>>(Wq, bq, Wk, Wv, bv, Ws, bs);
    kwc<<<6144, 256>>>(wh, wf);
    k1m<<<512, 256>>>(y);
    k2m<<<dim3(8, 64, 2), 256>>>();
    k3a<<<64, 256>>>();
    k3b<<<dim3(16, 64), 128>>>(y);
    k3c<<<128, 256>>>();
    k4 <<<32768, 256>>>(y, out);
}

// round 11
// speedup vs baseline: 1.3669x; 1.3669x over previous
#include <cuda_runtime.h>
#include <cuda_bf16.h>
#include <cstdint>

typedef unsigned long long ull;

// B=64, T=1024, TF=512, S=1536, D=512, F=32
#define NROW 65536
#define INV_SCALE 0.04419417382415922f   // 1/sqrt(512)
#define LOG2E 1.4426950408889634f
#define CE_F (INV_SCALE * LOG2E)

// ---------------- scratch (static __device__, no allocs) ----------------
__device__ __nv_bfloat16 g_PmTb[64 * 512];           // PmT[n][c]: n<32 = A col, n>=32 = CC col
__device__ float g_c1[32];
__device__ float g_vb[512];
__device__ __nv_bfloat16 g_qzb[(size_t)NROW * 64];   // per row: qk*CE+c1*CE [32] | z [32]
__device__ __nv_bfloat16 g_wbf[(size_t)64 * 1536 * 32];
__device__ float g_h[NROW];
__device__ float g_logits[NROW];
__device__ float g_P[NROW];
__device__ float g_fp[8 * 64 * 512];                 // partial final sums (8 t-chunks)
__device__ float g_final[64 * 512];

// ---------------- helpers ----------------
__device__ __forceinline__ float ex2f(float x) {
    float r; asm("ex2.approx.ftz.f32 %0, %1;" : "=f"(r) : "f"(x)); return r;
}

// m16n8k16 row.col bf16 -> f32 (sm_80+, no arch-specific suffix)
__device__ __forceinline__ void mma16816(float& d0, float& d1, float& d2, float& d3,
                                         uint32_t a0, uint32_t a1, uint32_t a2, uint32_t a3,
                                         uint32_t b0, uint32_t b1) {
    asm volatile("mma.sync.aligned.m16n8k16.row.col.f32.bf16.bf16.f32 "
                 "{%0,%1,%2,%3}, {%4,%5,%6,%7}, {%8,%9}, {%0,%1,%2,%3};"
                 : "+f"(d0), "+f"(d1), "+f"(d2), "+f"(d3)
                 : "r"(a0), "r"(a1), "r"(a2), "r"(a3), "r"(b0), "r"(b1));
}

__device__ __forceinline__ uint32_t packbf(float2 p) {
    __nv_bfloat162 v = __floats2bfloat162_rn(p.x, p.y);
    return *(uint32_t*)&v;
}

__device__ __forceinline__ uint32_t smem_u32(const void* p) {
    uint32_t a;
    asm("{ .reg .u64 t; cvta.to.shared.u64 t, %1; cvt.u32.u64 %0, t; }" : "=r"(a) : "l"(p));
    return a;
}

#define CP_ASYNC16(dst_u32, src) \
    asm volatile("cp.async.cg.shared.global [%0], [%1], 16;" :: "r"(dst_u32), "l"(src))
#define CP_COMMIT() asm volatile("cp.async.commit_group;" ::: "memory")
#define CP_WAIT(n)  asm volatile("cp.async.wait_group %0;" :: "n"(n) : "memory")

// ---------------------------------------------------------------------------
// K0: weight precompute.  grid=512 (c), block=128.
// ---------------------------------------------------------------------------
__global__ __launch_bounds__(128) void k0(
    const float* __restrict__ Wq, const float* __restrict__ bq,
    const float* __restrict__ Wk, const float* __restrict__ Wv,
    const float* __restrict__ bv, const float* __restrict__ Ws,
    const float* __restrict__ bs)
{
    __shared__ float sWq[512], sWsc[512];
    int c = blockIdx.x;
    for (int i = threadIdx.x; i < 512; i += 128) {
        sWq[i]  = Wq[c * 512 + i];
        sWsc[i] = Ws[i * 512 + c];
    }
    __syncthreads();
    int t = threadIdx.x;
    if (t < 32) {
        const float* wk = Wk + t * 512;
        float acc = 0.f;
        #pragma unroll 8
        for (int d = 0; d < 512; d++) acc = fmaf(sWq[d], wk[d], acc);
        g_PmTb[t * 512 + c] = __float2bfloat16(acc);
    } else if (t < 64) {
        const float* wv = Wv + (t - 32) * 512;
        float acc = 0.f;
        #pragma unroll 8
        for (int d = 0; d < 512; d++) acc = fmaf(wv[d], sWsc[d], acc);
        g_PmTb[t * 512 + c] = __float2bfloat16(acc);
    } else if (t == 64) {
        float acc = bs[c];
        for (int d = 0; d < 512; d++) acc = fmaf(bv[d], sWsc[d], acc);
        g_vb[c] = acc;
    } else if (t >= 96 && c == 0) {
        const float* wk = Wk + (t - 96) * 512;
        float acc = 0.f;
        for (int d = 0; d < 512; d++) acc = fmaf(bq[d], wk[d], acc);
        g_c1[t - 96] = acc;
    }
}

// ---------------------------------------------------------------------------
// K1M: qz = y @ PmT^T via bf16 mma.sync; fused h = y . vb.
// ---------------------------------------------------------------------------
__global__ __launch_bounds__(256) void k1m(const float* __restrict__ y)
{
    __shared__ __align__(16) char sB[64 * 528];   // 33792 B
    __shared__ float svb[512];
    __shared__ float sc1[32];

    int tid = threadIdx.x;
    int w = tid >> 5, lane = tid & 31;
    int g = lane >> 2, t = lane & 3;
    int R = blockIdx.x * 128 + w * 16;

    for (int i = tid; i < 512; i += 256) svb[i] = g_vb[i];
    if (tid < 32) sc1[tid] = g_c1[tid];

    float acc[8][4];
    #pragma unroll
    for (int n = 0; n < 8; n++) {
        acc[n][0] = 0.f; acc[n][1] = 0.f; acc[n][2] = 0.f; acc[n][3] = 0.f;
    }
    float ha = 0.f, hb = 0.f;

    const float* rowA = y + (size_t)(R + g) * 512;
    const float* rowB = y + (size_t)(R + g + 8) * 512;

    for (int half = 0; half < 2; half++) {
        __syncthreads();
        for (int i = tid; i < 2048; i += 256) {
            int r = i >> 5, seg = i & 31;
            *(uint4*)(sB + r * 528 + seg * 16) =
                *(const uint4*)(g_PmTb + (size_t)r * 512 + half * 256 + seg * 8);
        }
        __syncthreads();

        #pragma unroll 4
        for (int ks = 0; ks < 16; ks++) {
            int kg = half * 256 + ks * 16;
            int c  = kg + 2 * t;
            float2 p0 = *(const float2*)(rowA + c);
            float2 p1 = *(const float2*)(rowB + c);
            float2 p2 = *(const float2*)(rowA + c + 8);
            float2 p3 = *(const float2*)(rowB + c + 8);
            ha += p0.x * svb[c] + p0.y * svb[c + 1] + p2.x * svb[c + 8] + p2.y * svb[c + 9];
            hb += p1.x * svb[c] + p1.y * svb[c + 1] + p3.x * svb[c + 8] + p3.y * svb[c + 9];
            uint32_t a0 = packbf(p0), a1 = packbf(p1), a2 = packbf(p2), a3 = packbf(p3);
            const char* bbase = sB + g * 528 + 4 * t + 32 * ks;
            #pragma unroll
            for (int n = 0; n < 8; n++) {
                uint32_t b0 = *(const uint32_t*)(bbase + n * (8 * 528));
                uint32_t b1 = *(const uint32_t*)(bbase + n * (8 * 528) + 16);
                mma16816(acc[n][0], acc[n][1], acc[n][2], acc[n][3], a0, a1, a2, a3, b0, b1);
            }
        }
    }
    ha += __shfl_xor_sync(~0u, ha, 1); ha += __shfl_xor_sync(~0u, ha, 2);
    hb += __shfl_xor_sync(~0u, hb, 1); hb += __shfl_xor_sync(~0u, hb, 2);
    if (t == 0) { g_h[R + g] = ha; g_h[R + g + 8] = hb; }

    #pragma unroll
    for (int n = 0; n < 8; n++) {
        int col = n * 8 + 2 * t;
        float add0 = (n < 4) ? sc1[col] : 0.f;
        float add1 = (n < 4) ? sc1[col + 1] : 0.f;
        float sc   = (n < 4) ? CE_F : 1.0f;
        float v00 = (acc[n][0] + add0) * sc, v01 = (acc[n][1] + add1) * sc;
        float v10 = (acc[n][2] + add0) * sc, v11 = (acc[n][3] + add1) * sc;
        *(__nv_bfloat162*)(g_qzb + (size_t)(R + g) * 64 + col)     = __floats2bfloat162_rn(v00, v01);
        *(__nv_bfloat162*)(g_qzb + (size_t)(R + g + 8) * 64 + col) = __floats2bfloat162_rn(v10, v11);
    }
}

// ---------------------------------------------------------------------------
// KWC: weather -> bf16 contiguous [b][1536][32] (hist then fore).
// ---------------------------------------------------------------------------
__global__ __launch_bounds__(256) void kwc(const float* __restrict__ wh,
                                           const float* __restrict__ wf)
{
    int ip = blockIdx.x * 256 + threadIdx.x;
    int b = ip / 24576;
    int r = ip - b * 24576;
    float2 v;
    if (r < 16384) v = ((const float2*)(wh + (size_t)b * 32768))[r];
    else           v = ((const float2*)(wf + (size_t)b * 16384))[r - 16384];
    ((__nv_bfloat162*)g_wbf)[(size_t)b * 24576 + r] = __floats2bfloat162_rn(v.x, v.y);
}

// ---------------------------------------------------------------------------
// K2M: micro-attention via bf16 mma.sync (round-7 shape, s unsplit) with
// cp.async double-buffered weather staging.
// grid (8 t-tiles, 64 b), 256 threads; 6 chunks of 256 s, 2x20KB buffers.
// Each thread issues 4 cp.async(16B) per chunk; chunk c+2 copies overlap
// chunk c compute. Writes logits directly.
// ---------------------------------------------------------------------------
__global__ __launch_bounds__(256) void k2m()
{
    __shared__ __align__(16) char sW[2][256 * 80];   // 2 x 20480 B

    int tid = threadIdx.x;
    int w = tid >> 5, lane = tid & 31;
    int g = lane >> 2, t = lane & 3;
    int b = blockIdx.y;
    size_t Rbase = (size_t)b * 1024 + blockIdx.x * 128 + w * 16;

    // A fragments: qk (pre-scaled) | z
    uint32_t qa[2][4], za[2][4];
    #pragma unroll
    for (int ks = 0; ks < 2; ks++) {
        int c = 16 * ks + 2 * t;
        qa[ks][0] = *(const uint32_t*)(g_qzb + (Rbase + g) * 64 + c);
        qa[ks][1] = *(const uint32_t*)(g_qzb + (Rbase + g + 8) * 64 + c);
        qa[ks][2] = *(const uint32_t*)(g_qzb + (Rbase + g) * 64 + c + 8);
        qa[ks][3] = *(const uint32_t*)(g_qzb + (Rbase + g + 8) * 64 + c + 8);
        za[ks][0] = *(const uint32_t*)(g_qzb + (Rbase + g) * 64 + 32 + c);
        za[ks][1] = *(const uint32_t*)(g_qzb + (Rbase + g + 8) * 64 + 32 + c);
        za[ks][2] = *(const uint32_t*)(g_qzb + (Rbase + g) * 64 + 32 + c + 8);
        za[ks][3] = *(const uint32_t*)(g_qzb + (Rbase + g + 8) * 64 + 32 + c + 8);
    }

    // per-thread staging targets: 4 x 16B per chunk
    int srow = tid >> 2, sseg = tid & 3;           // rows tid/4 + {0,64,128,192}
    uint32_t dst0 = smem_u32(sW[0]) + (uint32_t)srow * 80 + sseg * 16;
    uint32_t dst1 = smem_u32(sW[1]) + (uint32_t)srow * 80 + sseg * 16;
    const char* wsrc = (const char*)(g_wbf + (size_t)b * 1536 * 32) + (size_t)tid * 16;

    // prologue: issue chunks 0 and 1
    #pragma unroll
    for (int kk = 0; kk < 4; kk++)
        CP_ASYNC16(dst0 + kk * (64 * 80), wsrc + (size_t)0 * 16384 + kk * 4096);
    CP_COMMIT();
    #pragma unroll
    for (int kk = 0; kk < 4; kk++)
        CP_ASYNC16(dst1 + kk * (64 * 80), wsrc + (size_t)1 * 16384 + kk * 4096);
    CP_COMMIT();

    float dena = 0.f, numa = 0.f, denb = 0.f, numb = 0.f;

    #pragma unroll 1
    for (int c = 0; c < 6; c++) {
        CP_WAIT(1);            // chunk c complete (c+1 may be in flight)
        __syncthreads();
        const char* buf = sW[c & 1];

        #pragma unroll 2
        for (int sb = 0; sb < 32; sb++) {
            const char* base = buf + (sb * 8 + g) * 80 + 4 * t;
            uint32_t b0 = *(const uint32_t*)(base);
            uint32_t b1 = *(const uint32_t*)(base + 16);
            uint32_t b2 = *(const uint32_t*)(base + 32);
            uint32_t b3 = *(const uint32_t*)(base + 48);
            float s0 = 0.f, s1 = 0.f, s2 = 0.f, s3 = 0.f;
            float z0 = 0.f, z1 = 0.f, z2 = 0.f, z3 = 0.f;
            mma16816(s0, s1, s2, s3, qa[0][0], qa[0][1], qa[0][2], qa[0][3], b0, b1);
            mma16816(s0, s1, s2, s3, qa[1][0], qa[1][1], qa[1][2], qa[1][3], b2, b3);
            mma16816(z0, z1, z2, z3, za[0][0], za[0][1], za[0][2], za[0][3], b0, b1);
            mma16816(z0, z1, z2, z3, za[1][0], za[1][1], za[1][2], za[1][3], b2, b3);
            float e0 = ex2f(s0), e1 = ex2f(s1), e2 = ex2f(s2), e3 = ex2f(s3);
            dena += e0 + e1;
            numa = fmaf(e0, z0, fmaf(e1, z1, numa));
            denb += e2 + e3;
            numb = fmaf(e2, z2, fmaf(e3, z3, numb));
        }

        __syncthreads();       // all readers done with buf before refill
        if (c + 2 < 6) {
            uint32_t dst = (c & 1) ? dst1 : dst0;
            #pragma unroll
            for (int kk = 0; kk < 4; kk++)
                CP_ASYNC16(dst + kk * (64 * 80), wsrc + (size_t)(c + 2) * 16384 + kk * 4096);
        }
        CP_COMMIT();           // keep group count in lockstep (empty group ok)
    }

    dena += __shfl_xor_sync(~0u, dena, 1); dena += __shfl_xor_sync(~0u, dena, 2);
    numa += __shfl_xor_sync(~0u, numa, 1); numa += __shfl_xor_sync(~0u, numa, 2);
    denb += __shfl_xor_sync(~0u, denb, 1); denb += __shfl_xor_sync(~0u, denb, 2);
    numb += __shfl_xor_sync(~0u, numb, 1); numb += __shfl_xor_sync(~0u, numb, 2);
    if (t == 0) {
        size_t r0 = Rbase + g, r1 = Rbase + g + 8;
        g_logits[r0] = (numa / dena + g_h[r0]) * INV_SCALE;
        g_logits[r1] = (numb / denb + g_h[r1]) * INV_SCALE;
    }
}

// ---------------------------------------------------------------------------
// K3a: P = softmax over t (per batch).
// ---------------------------------------------------------------------------
__global__ __launch_bounds__(256) void k3a()
{
    __shared__ float red[256];
    int b = blockIdx.x, tid = threadIdx.x;
    float l[4];
    #pragma unroll
    for (int k = 0; k < 4; k++) l[k] = g_logits[b * 1024 + tid + 256 * k];
    float m = fmaxf(fmaxf(l[0], l[1]), fmaxf(l[2], l[3]));
    red[tid] = m; __syncthreads();
    for (int o = 128; o; o >>= 1) { if (tid < o) red[tid] = fmaxf(red[tid], red[tid + o]); __syncthreads(); }
    m = red[0]; __syncthreads();
    float e[4], s = 0.f;
    #pragma unroll
    for (int k = 0; k < 4; k++) { e[k] = ex2f((l[k] - m) * LOG2E); s += e[k]; }
    red[tid] = s; __syncthreads();
    for (int o = 128; o; o >>= 1) { if (tid < o) red[tid] += red[tid + o]; __syncthreads(); }
    float inv = 1.0f / red[0];
    #pragma unroll
    for (int k = 0; k < 4; k++) g_P[b * 1024 + tid + 256 * k] = e[k] * inv;
}

// ---------------------------------------------------------------------------
// K3b: partial final sums, 8 t-chunks of 128, unroll 8 (MLP fix).
// grid (8 tc, 64 b), 128 threads.
// ---------------------------------------------------------------------------
__global__ __launch_bounds__(128) void k3b(const float* __restrict__ y)
{
    int tc = blockIdx.x, b = blockIdx.y, tid = threadIdx.x;
    const float4* yb = (const float4*)(y + ((size_t)b * 1024 + tc * 128) * 512);
    const float*  Pp = g_P + b * 1024 + tc * 128;
    float4 acc = make_float4(0.f, 0.f, 0.f, 0.f);
    #pragma unroll 8
    for (int t = 0; t < 128; t++) {
        float p = Pp[t];
        float4 v = yb[(size_t)t * 128 + tid];
        acc.x = fmaf(p, v.x, acc.x); acc.y = fmaf(p, v.y, acc.y);
        acc.z = fmaf(p, v.z, acc.z); acc.w = fmaf(p, v.w, acc.w);
    }
    ((float4*)g_fp)[((size_t)tc * 64 + b) * 128 + tid] = acc;
}

// ---------------------------------------------------------------------------
// K3c: collapse 8 partials -> g_final[64*512].
// ---------------------------------------------------------------------------
__global__ __launch_bounds__(256) void k3c()
{
    int i = blockIdx.x * 256 + threadIdx.x;   // 0..32767
    float s = 0.f;
    #pragma unroll
    for (int c = 0; c < 8; c++) s += g_fp[(size_t)c * 32768 + i];
    g_final[i] = s;
}

// ---------------------------------------------------------------------------
// K4: out = y + final (broadcast over t).
// ---------------------------------------------------------------------------
__global__ __launch_bounds__(256) void k4(const float* __restrict__ y, float* __restrict__ out)
{
    size_t idx = (size_t)blockIdx.x * 256 + threadIdx.x;   // float4 index
    int b  = (int)(idx >> 17);
    int d4 = (int)(idx & 127);
    float4 f = ((const float4*)g_final)[b * 128 + d4];
    float4 v = ((const float4*)y)[idx];
    float4 o;
    o.x = v.x + f.x; o.y = v.y + f.y; o.z = v.z + f.z; o.w = v.w + f.w;
    ((float4*)out)[idx] = o;
}

// ---------------------------------------------------------------------------
extern "C" void kernel_launch(void* const* d_in, const int* in_sizes, int n_in,
                              void* d_out, int out_size)
{
    const float* y  = (const float*)d_in[0];
    const float* wh = (const float*)d_in[1];
    const float* wf = (const float*)d_in[2];
    const float* Wq = (const float*)d_in[3];
    const float* bq = (const float*)d_in[4];
    const float* Wk = (const float*)d_in[5];
    // d_in[6] = bk: cancels in softmax over s
    const float* Wv = (const float*)d_in[7];
    const float* bv = (const float*)d_in[8];
    const float* Ws = (const float*)d_in[9];
    const float* bs = (const float*)d_in[10];
    float* out = (float*)d_out;

    k0 <<<512, 128>>>(Wq, bq, Wk, Wv, bv, Ws, bs);
    kwc<<<6144, 256>>>(wh, wf);
    k1m<<<512, 256>>>(y);
    k2m<<<dim3(8, 64), 256>>>();
    k3a<<<64, 256>>>();
    k3b<<<dim3(8, 64), 128>>>(y);
    k3c<<<128, 256>>>();
    k4 <<<32768, 256>>>(y, out);
}